// round 17
// baseline (speedup 1.0000x reference)
#include <cuda_runtime.h>
#include <cuda_bf16.h>
#include <math.h>

#define BATCH 16
#define SEQ   2048
#define HD    64
#define BQ    128
#define BK    64
#define THREADS 256
#define LDB   72              // bf16 smem row stride: 144B => conflict-free ldmatrix
#define LDS_STG 68            // fp32 staging row stride: conflict-free convert loads
#define MASK_ELEMS (16LL * 2048 * 2048)

// byte offsets in dynamic smem
#define KHI_B 0
#define KLO_B (64 * LDB * 2)          // 9216
#define VHI_B (2 * 64 * LDB * 2)      // 18432
#define VLO_B (3 * 64 * LDB * 2)      // 27648
#define STG_B (4 * 64 * LDB * 2)      // 36864
#define STG_TENSOR (64 * LDS_STG * 4) // 17408 bytes (16B-aligned)
#define SMEM_TOTAL (STG_B + 4 * STG_TENSOR)   // 106496 B -> 2 CTAs/SM fits

// 1 => mask stored as int32 elements (bool upcast by harness); 0 => byte mask
__device__ int g_mask_is_wide;

__global__ void detect_mask_kernel(const unsigned char* __restrict__ m)
{
    const int tid = threadIdx.x;
    int nonzero = 0;
    for (int i = tid; i < 4096; i += 32)
        if ((i & 3) && m[i]) nonzero = 1;
    const unsigned any = __ballot_sync(0xffffffffu, nonzero);
    if (tid == 0) g_mask_is_wide = (any == 0u) ? 1 : 0;
}

__device__ __forceinline__ unsigned pack2(float x, float y)
{
    unsigned r;
    asm("cvt.rn.bf16x2.f32 %0, %1, %2;" : "=r"(r) : "f"(y), "f"(x));
    return r;
}
__device__ __forceinline__ void split2(float x, float y, unsigned& h, unsigned& l)
{
    h = pack2(x, y);
    const float hx = __uint_as_float(h << 16);
    const float hy = __uint_as_float(h & 0xffff0000u);
    l = pack2(x - hx, y - hy);
}

__device__ __forceinline__ void mma_bf16(float d[4], const unsigned a[4],
                                         unsigned b0, unsigned b1)
{
    asm("mma.sync.aligned.m16n8k16.row.col.f32.bf16.bf16.f32 "
        "{%0,%1,%2,%3},{%4,%5,%6,%7},{%8,%9},{%0,%1,%2,%3};"
        : "+f"(d[0]), "+f"(d[1]), "+f"(d[2]), "+f"(d[3])
        : "r"(a[0]), "r"(a[1]), "r"(a[2]), "r"(a[3]), "r"(b0), "r"(b1));
}
__device__ __forceinline__ void ldsm4(unsigned& r0, unsigned& r1,
                                      unsigned& r2, unsigned& r3, unsigned a)
{
    asm volatile("ldmatrix.sync.aligned.m8n8.x4.shared.b16 {%0,%1,%2,%3},[%4];"
                 : "=r"(r0), "=r"(r1), "=r"(r2), "=r"(r3) : "r"(a));
}
__device__ __forceinline__ void ldsm4t(unsigned& r0, unsigned& r1,
                                       unsigned& r2, unsigned& r3, unsigned a)
{
    asm volatile("ldmatrix.sync.aligned.m8n8.x4.trans.shared.b16 {%0,%1,%2,%3},[%4];"
                 : "=r"(r0), "=r"(r1), "=r"(r2), "=r"(r3) : "r"(a));
}
__device__ __forceinline__ void cp16(unsigned dst, const void* src)
{
    asm volatile("cp.async.ca.shared.global [%0], [%1], 16;" :: "r"(dst), "l"(src));
}
#define CP_COMMIT() asm volatile("cp.async.commit_group;")
#define CP_WAIT0()  asm volatile("cp.async.wait_group 0;")

__global__ __launch_bounds__(THREADS, 2)
void attn_kernel(const float* __restrict__ q,
                 const float* __restrict__ k,
                 const float* __restrict__ v,
                 const unsigned char* __restrict__ mask,
                 float* __restrict__ out)
{
    extern __shared__ __align__(16) char smraw[];
    __nv_bfloat16* KhiP = (__nv_bfloat16*)(smraw + KHI_B);
    __nv_bfloat16* KloP = (__nv_bfloat16*)(smraw + KLO_B);
    __nv_bfloat16* VhiP = (__nv_bfloat16*)(smraw + VHI_B);
    __nv_bfloat16* VloP = (__nv_bfloat16*)(smraw + VLO_B);

    const int tid  = threadIdx.x;
    const int warp = tid >> 5;
    const int lane = tid & 31;
    const int g    = lane >> 2;
    const int c    = lane & 3;
    const int b    = blockIdx.y;
    const int q0   = blockIdx.x * BQ;
    const int wide = g_mask_is_wide;

    const int row_lo = warp * 16 + g;

    const unsigned sm_base = (unsigned)__cvta_generic_to_shared(smraw);
    const int r8    = lane & 7;
    const int matid = lane >> 3;
    const unsigned qk_lane = 2u * ((unsigned)(8 * (matid >> 1) + r8) * LDB + 8 * (matid & 1));
    const unsigned pv_lane = 2u * ((unsigned)(8 * (matid & 1) + r8) * LDB + 8 * (matid >> 1));
    const unsigned khi_b = sm_base + KHI_B + qk_lane;
    const unsigned klo_b = sm_base + KLO_B + qk_lane;
    const unsigned vhi_b = sm_base + VHI_B + pv_lane;
    const unsigned vlo_b = sm_base + VLO_B + pv_lane;

    const int krow = tid >> 2;              // 0..63
    const int cb   = (tid & 3) * 16;        // float offset 0,16,32,48

    // issue cp.async of K/V tile (key offset k0n) into staging stage st
    auto stage_fetch = [&](int k0n, int st) {
        const unsigned kdst = sm_base + STG_B + (unsigned)(st * 2 * STG_TENSOR)
                            + (unsigned)((krow * LDS_STG + cb) * 4);
        const unsigned vdst = kdst + STG_TENSOR;
        const float* kp = k + ((size_t)b * SEQ + k0n + krow) * HD + cb;
        const float* vp = v + ((size_t)b * SEQ + k0n + krow) * HD + cb;
#pragma unroll
        for (int j = 0; j < 4; j++) {
            cp16(kdst + 16u * j, kp + 4 * j);
            cp16(vdst + 16u * j, vp + 4 * j);
        }
        CP_COMMIT();
    };

    // ---- Q fragments in registers (hi/lo bf16 split), loaded once ----
    unsigned qh[4][4], ql[4][4];
    {
        const float* qlo_p = q + ((size_t)b * SEQ + q0 + row_lo) * HD;
        const float* qhi_p = qlo_p + 8 * HD;
#pragma unroll
        for (int s = 0; s < 4; s++) {
            float2 f0 = *(const float2*)(qlo_p + 16 * s + 2 * c);
            float2 f1 = *(const float2*)(qhi_p + 16 * s + 2 * c);
            float2 f2 = *(const float2*)(qlo_p + 16 * s + 2 * c + 8);
            float2 f3 = *(const float2*)(qhi_p + 16 * s + 2 * c + 8);
            split2(f0.x, f0.y, qh[s][0], ql[s][0]);
            split2(f1.x, f1.y, qh[s][1], ql[s][1]);
            split2(f2.x, f2.y, qh[s][2], ql[s][2]);
            split2(f3.x, f3.y, qh[s][3], ql[s][3]);
        }
    }

    float o[8][4];
#pragma unroll
    for (int t = 0; t < 8; t++)
#pragma unroll
        for (int r = 0; r < 4; r++) o[t][r] = 0.f;

    float mr_lo = -INFINITY, mr_hi = -INFINITY, l_lo = 0.f, l_hi = 0.f;

    // preloop: stage tile 0
    stage_fetch(0, 0);

    const size_t mrow_lo_base = ((size_t)b * SEQ + q0 + row_lo) * SEQ + 2 * c;
    const size_t mrow_hi_base = mrow_lo_base + 8 * SEQ;

    for (int kt = 0; kt < SEQ / BK; kt++) {
        const int k0 = kt * BK;
        const int st = kt & 1;

        CP_WAIT0();          // staging stage st complete (self-consumed regions)
        __syncthreads();     // previous tile's bf16 readers are done

        // ---- convert staging fp32 -> split bf16 tiles ----
        {
            const float* stgK = (const float*)(smraw + STG_B + st * 2 * STG_TENSOR);
            const float* stgV = (const float*)(smraw + STG_B + st * 2 * STG_TENSOR + STG_TENSOR);
#pragma unroll
            for (int j = 0; j < 4; j++) {
                const float4 f = *(const float4*)(stgK + krow * LDS_STG + cb + 4 * j);
                unsigned h01, l01, h23, l23;
                split2(f.x, f.y, h01, l01);
                split2(f.z, f.w, h23, l23);
                *(uint2*)&KhiP[krow * LDB + cb + 4 * j] = make_uint2(h01, h23);
                *(uint2*)&KloP[krow * LDB + cb + 4 * j] = make_uint2(l01, l23);
            }
#pragma unroll
            for (int j = 0; j < 4; j++) {
                const float4 f = *(const float4*)(stgV + krow * LDS_STG + cb + 4 * j);
                unsigned h01, l01, h23, l23;
                split2(f.x, f.y, h01, l01);
                split2(f.z, f.w, h23, l23);
                *(uint2*)&VhiP[krow * LDB + cb + 4 * j] = make_uint2(h01, h23);
                *(uint2*)&VloP[krow * LDB + cb + 4 * j] = make_uint2(l01, l23);
            }
        }

        // ---- stage next tile (async; lands during compute) ----
        {
            const int kn = (kt + 1 < SEQ / BK) ? (k0 + BK) : k0;
            stage_fetch(kn, st ^ 1);
        }
        __syncthreads();     // bf16 tiles ready

        // ---- mask loads, packed immediately into 4 bitmasks ----
        unsigned mbA = 0, mbB = 0, mbC = 0, mbD = 0;
        if (wide) {
            const int* mi = (const int*)mask;
#pragma unroll
            for (int T = 0; T < 8; T++) {
                const int2 u = *(const int2*)(mi + mrow_lo_base + k0 + 8 * T);
                const int2 w = *(const int2*)(mi + mrow_hi_base + k0 + 8 * T);
                mbA |= (u.x ? 1u : 0u) << T;
                mbB |= (u.y ? 1u : 0u) << T;
                mbC |= (w.x ? 1u : 0u) << T;
                mbD |= (w.y ? 1u : 0u) << T;
            }
        } else {
#pragma unroll
            for (int T = 0; T < 8; T++) {
                const uchar2 u = *(const uchar2*)(mask + mrow_lo_base + k0 + 8 * T);
                const uchar2 w = *(const uchar2*)(mask + mrow_hi_base + k0 + 8 * T);
                mbA |= (u.x ? 1u : 0u) << T;
                mbB |= (u.y ? 1u : 0u) << T;
                mbC |= (w.x ? 1u : 0u) << T;
                mbD |= (w.y ? 1u : 0u) << T;
            }
        }

        // ---- S = Q K^T via 3x split-bf16 mma ----
        float sacc[8][4];
#pragma unroll
        for (int T = 0; T < 8; T++)
#pragma unroll
            for (int r = 0; r < 4; r++) sacc[T][r] = 0.f;

#pragma unroll
        for (int s = 0; s < 4; s++) {
#pragma unroll
            for (int tp = 0; tp < 4; tp++) {
                const unsigned off = (unsigned)(tp * (16 * LDB * 2) + s * 32);
                unsigned h0a, h1a, h0b, h1b, l0a, l1a, l0b, l1b;
                ldsm4(h0a, h1a, h0b, h1b, khi_b + off);
                ldsm4(l0a, l1a, l0b, l1b, klo_b + off);
                mma_bf16(sacc[2 * tp],     qh[s], h0a, h1a);
                mma_bf16(sacc[2 * tp],     qh[s], l0a, l1a);
                mma_bf16(sacc[2 * tp],     ql[s], h0a, h1a);
                mma_bf16(sacc[2 * tp + 1], qh[s], h0b, h1b);
                mma_bf16(sacc[2 * tp + 1], qh[s], l0b, l1b);
                mma_bf16(sacc[2 * tp + 1], ql[s], h0b, h1b);
            }
        }

        // ---- scale (1/8) + mask (True -> 1e-9) ----
#pragma unroll
        for (int T = 0; T < 8; T++) {
            sacc[T][0] = ((mbA >> T) & 1u) ? 1e-9f : sacc[T][0] * 0.125f;
            sacc[T][1] = ((mbB >> T) & 1u) ? 1e-9f : sacc[T][1] * 0.125f;
            sacc[T][2] = ((mbC >> T) & 1u) ? 1e-9f : sacc[T][2] * 0.125f;
            sacc[T][3] = ((mbD >> T) & 1u) ? 1e-9f : sacc[T][3] * 0.125f;
        }

        // ---- online softmax ----
        float tmx_lo = sacc[0][0], tmx_hi = sacc[0][2];
#pragma unroll
        for (int T = 0; T < 8; T++) {
            tmx_lo = fmaxf(tmx_lo, fmaxf(sacc[T][0], sacc[T][1]));
            tmx_hi = fmaxf(tmx_hi, fmaxf(sacc[T][2], sacc[T][3]));
        }
#pragma unroll
        for (int off = 1; off < 4; off <<= 1) {
            tmx_lo = fmaxf(tmx_lo, __shfl_xor_sync(0xffffffffu, tmx_lo, off));
            tmx_hi = fmaxf(tmx_hi, __shfl_xor_sync(0xffffffffu, tmx_hi, off));
        }

        const float mn_lo = fmaxf(mr_lo, tmx_lo);
        const float mn_hi = fmaxf(mr_hi, tmx_hi);
        const float cr_lo = __expf(mr_lo - mn_lo);
        const float cr_hi = __expf(mr_hi - mn_hi);
        mr_lo = mn_lo; mr_hi = mn_hi;

#pragma unroll
        for (int t = 0; t < 8; t++) {
            o[t][0] *= cr_lo; o[t][1] *= cr_lo;
            o[t][2] *= cr_hi; o[t][3] *= cr_hi;
        }

        float sum_lo = 0.f, sum_hi = 0.f;
        unsigned phA[8], phB[8], plA[8], plB[8];
#pragma unroll
        for (int T = 0; T < 8; T++) {
            const float p0 = __expf(sacc[T][0] - mn_lo);
            const float p1 = __expf(sacc[T][1] - mn_lo);
            const float p2 = __expf(sacc[T][2] - mn_hi);
            const float p3 = __expf(sacc[T][3] - mn_hi);
            sum_lo += p0 + p1;
            sum_hi += p2 + p3;
            split2(p0, p1, phA[T], plA[T]);
            split2(p2, p3, phB[T], plB[T]);
        }
#pragma unroll
        for (int off = 1; off < 4; off <<= 1) {
            sum_lo += __shfl_xor_sync(0xffffffffu, sum_lo, off);
            sum_hi += __shfl_xor_sync(0xffffffffu, sum_hi, off);
        }
        l_lo = l_lo * cr_lo + sum_lo;
        l_hi = l_hi * cr_hi + sum_hi;

        // ---- O += P V via 3x split-bf16 mma ----
#pragma unroll
        for (int s = 0; s < 4; s++) {
            const unsigned ah[4] = {phA[2 * s], phB[2 * s], phA[2 * s + 1], phB[2 * s + 1]};
            const unsigned al[4] = {plA[2 * s], plB[2 * s], plA[2 * s + 1], plB[2 * s + 1]};
#pragma unroll
            for (int tp = 0; tp < 4; tp++) {
                const unsigned off = (unsigned)(s * (16 * LDB * 2) + tp * 32);
                unsigned h0a, h1a, h0b, h1b, l0a, l1a, l0b, l1b;
                ldsm4t(h0a, h1a, h0b, h1b, vhi_b + off);
                ldsm4t(l0a, l1a, l0b, l1b, vlo_b + off);
                mma_bf16(o[2 * tp],     ah, h0a, h1a);
                mma_bf16(o[2 * tp],     ah, l0a, l1a);
                mma_bf16(o[2 * tp],     al, h0a, h1a);
                mma_bf16(o[2 * tp + 1], ah, h0b, h1b);
                mma_bf16(o[2 * tp + 1], ah, l0b, l1b);
                mma_bf16(o[2 * tp + 1], al, h0b, h1b);
            }
        }
    }

    // ---- epilogue ----
    const float inv_lo = 1.f / l_lo;
    const float inv_hi = 1.f / l_hi;
    float* olo_p = out + ((size_t)b * SEQ + q0 + row_lo) * HD;
    float* ohi_p = olo_p + 8 * HD;
#pragma unroll
    for (int t = 0; t < 8; t++) {
        *(float2*)(olo_p + 8 * t + 2 * c) = make_float2(o[t][0] * inv_lo, o[t][1] * inv_lo);
        *(float2*)(ohi_p + 8 * t + 2 * c) = make_float2(o[t][2] * inv_hi, o[t][3] * inv_hi);
    }
}

extern "C" void kernel_launch(void* const* d_in, const int* in_sizes, int n_in,
                              void* d_out, int out_size)
{
    (void)out_size;
    int mask_idx = -1;
    for (int i = 0; i < n_in; i++)
        if ((long long)in_sizes[i] == MASK_ELEMS) { mask_idx = i; break; }
    if (mask_idx < 0) mask_idx = 3;

    const float* qkv[3];
    int nq = 0;
    for (int i = 0; i < n_in && nq < 3; i++)
        if (i != mask_idx) qkv[nq++] = (const float*)d_in[i];

    const float* q = qkv[0];
    const float* k = qkv[1];
    const float* v = qkv[2];
    const unsigned char* mask = (const unsigned char*)d_in[mask_idx];
    float* out = (float*)d_out;

    cudaFuncSetAttribute(attn_kernel, cudaFuncAttributeMaxDynamicSharedMemorySize,
                         (int)SMEM_TOTAL);

    detect_mask_kernel<<<1, 32>>>(mask);

    dim3 grid(SEQ / BQ, BATCH);
    attn_kernel<<<grid, THREADS, SMEM_TOTAL>>>(q, k, v, mask, out);
}